// round 6
// baseline (speedup 1.0000x reference)
#include <cuda_runtime.h>
#include <cuda_bf16.h>
#include <math.h>
#include <stdint.h>

#define BATCH 512
#define INCAPS 1152
#define OUTCAPS 10
#define INDIM 8
#define OUTDIM 16
#define EPSF 1e-8f

// ---- scratch (device globals; no allocations allowed) ----
__device__ float g_h2[BATCH * 256 * 36];             // conv2 out [B,256,6,6]
__device__ float g_u[BATCH * INCAPS * INDIM];        // squashed capsules [B,1152,8]
__device__ float g_uhat[(long long)BATCH * INCAPS * OUTCAPS * OUTDIM]; // [B,1152,10,16]
__device__ int   g_pred[BATCH];
__device__ float g_sel[BATCH * OUTDIM];

// tensor-core conv2 operands
#define H1N (BATCH * 400 * 256)
#define W2N (256 * 20736)
__device__ __align__(256) __nv_bfloat16 g_h1hi[H1N];   // NHWC hi [b][pix][c]
__device__ __align__(256) __nv_bfloat16 g_h1lo[H1N];   // NHWC lo
__device__ __align__(256) __nv_bfloat16 g_w2hi[W2N];   // [chunk c][oc][64 ic]
__device__ __align__(256) __nv_bfloat16 g_w2lo[W2N];

// output layout (float32): caps | recon | pred
#define CAPS_OFF  0
#define RECON_OFF (BATCH * OUTCAPS * OUTDIM)              // 81920
#define PRED_OFF  (RECON_OFF + BATCH * 784)               // 483328

// ============================================================
// conv1 fused: x (*) w stride1 + bias, ReLU -> NHWC bf16 hi/lo directly.
// Per block: (image b, 16 channels). Results staged in padded smem, then
// written as [pix][16ch] 32B rows (2x uint4 per array).
// ============================================================
__global__ __launch_bounds__(256) void conv1_kernel(const float* __restrict__ x,
                                                    const float* __restrict__ w,
                                                    const float* __restrict__ bias) {
    __shared__ __align__(16) float img[784];
    __shared__ float wts[16 * 81];
    __shared__ float stage[16 * 401];
    int b = blockIdx.x, c0 = blockIdx.y * 16, t = threadIdx.x;
    for (int i = t; i < 784; i += 256) img[i] = x[b * 784 + i];
    for (int i = t; i < 16 * 81; i += 256) wts[i] = w[c0 * 81 + i];
    __syncthreads();
    for (int idx = t; idx < 1600; idx += 256) {
        int cl = idx / 100;
        int rem = idx % 100;
        int oy = rem / 5;
        int ox0 = (rem % 5) * 4;
        float bb = bias[c0 + cl];
        float a0 = bb, a1 = bb, a2 = bb, a3 = bb;
        const float* wp = &wts[cl * 81];
#pragma unroll
        for (int ky = 0; ky < 9; ky++) {
            const float4* ip = (const float4*)&img[(oy + ky) * 28 + ox0];
            float4 q0 = ip[0], q1 = ip[1], q2 = ip[2];
            float v[12] = {q0.x, q0.y, q0.z, q0.w, q1.x, q1.y, q1.z, q1.w,
                           q2.x, q2.y, q2.z, q2.w};
#pragma unroll
            for (int kx = 0; kx < 9; kx++) {
                float wv = wp[ky * 9 + kx];
                a0 += wv * v[kx];
                a1 += wv * v[kx + 1];
                a2 += wv * v[kx + 2];
                a3 += wv * v[kx + 3];
            }
        }
        float* sp = &stage[cl * 401 + oy * 20 + ox0];
        sp[0] = fmaxf(a0, 0.f);
        sp[1] = fmaxf(a1, 0.f);
        sp[2] = fmaxf(a2, 0.f);
        sp[3] = fmaxf(a3, 0.f);
    }
    __syncthreads();
    for (int p = t; p < 400; p += 256) {
        uint32_t hp[8], lp[8];
#pragma unroll
        for (int k = 0; k < 8; k++) {
            float v0 = stage[(2 * k) * 401 + p];
            float v1 = stage[(2 * k + 1) * 401 + p];
            __nv_bfloat16 h0 = __float2bfloat16(v0);
            __nv_bfloat16 h1 = __float2bfloat16(v1);
            float l0 = v0 - __bfloat162float(h0);
            float l1 = v1 - __bfloat162float(h1);
            __nv_bfloat16 lo0 = __float2bfloat16(l0);
            __nv_bfloat16 lo1 = __float2bfloat16(l1);
            hp[k] = (uint32_t)__bfloat16_as_ushort(h0) |
                    ((uint32_t)__bfloat16_as_ushort(h1) << 16);
            lp[k] = (uint32_t)__bfloat16_as_ushort(lo0) |
                    ((uint32_t)__bfloat16_as_ushort(lo1) << 16);
        }
        int off = (b * 400 + p) * 256 + c0;
        uint4* dh = (uint4*)(g_h1hi + off);
        uint4* dl = (uint4*)(g_h1lo + off);
        dh[0] = make_uint4(hp[0], hp[1], hp[2], hp[3]);
        dh[1] = make_uint4(hp[4], hp[5], hp[6], hp[7]);
        dl[0] = make_uint4(lp[0], lp[1], lp[2], lp[3]);
        dl[1] = make_uint4(lp[4], lp[5], lp[6], lp[7]);
    }
}

// ============================================================
// weight repack: c2w[oc][ic][81] fp32 -> [c=k*4+icc][oc][ici] bf16 hi/lo
// ============================================================
__global__ void repack_w2_kernel(const float* __restrict__ w) {
    int idx = blockIdx.x * 256 + threadIdx.x;
    if (idx >= W2N) return;
    int ici = idx & 63;
    int oc = (idx >> 6) & 255;
    int c = idx >> 14;           // 0..323
    int k = c >> 2, icc = c & 3;
    int ic = icc * 64 + ici;
    float v = w[(oc * 256 + ic) * 81 + k];
    __nv_bfloat16 hi = __float2bfloat16(v);
    float lo = v - __bfloat162float(hi);
    g_w2hi[idx] = hi;
    g_w2lo[idx] = __float2bfloat16(lo);
}

// ============================================================
// conv2 via HMMA: D[pos 128][oc 128] tiles, K = 81*256 in chunks of 64.
// hi/lo bf16 split (3 MMAs per step). 3-stage cp.async pipeline.
// ============================================================
#define NCHUNK 324
#define SMEM_STAGE 65536
#define SM_A(s) ((s) * SMEM_STAGE)          // Xhi 16K | Xlo 16K
#define SM_B(s) ((s) * SMEM_STAGE + 32768)  // Whi 16K | Wlo 16K
#define SMEM_BYTES (3 * SMEM_STAGE)
#define SWZ(x) ((x) ^ (((x) >> 3) & 0x70))

__device__ __forceinline__ uint32_t smem_u32(const void* p) {
    uint32_t a;
    asm("{ .reg .u64 t; cvta.to.shared.u64 t, %1; cvt.u32.u64 %0, t; }" : "=r"(a) : "l"(p));
    return a;
}
__device__ __forceinline__ void cp16(uint32_t dst, const void* src) {
    asm volatile("cp.async.cg.shared.global [%0], [%1], 16;" :: "r"(dst), "l"(src) : "memory");
}
#define LDMX4(r, addr)                                                          \
    asm volatile("ldmatrix.sync.aligned.m8n8.x4.shared.b16 {%0,%1,%2,%3}, [%4];" \
                 : "=r"((r)[0]), "=r"((r)[1]), "=r"((r)[2]), "=r"((r)[3])        \
                 : "r"(addr))
#define MMA(d, a, b0, b1)                                                        \
    asm volatile("mma.sync.aligned.m16n8k16.row.col.f32.bf16.bf16.f32 "          \
                 "{%0,%1,%2,%3}, {%4,%5,%6,%7}, {%8,%9}, {%0,%1,%2,%3};"         \
                 : "+f"((d)[0]), "+f"((d)[1]), "+f"((d)[2]), "+f"((d)[3])        \
                 : "r"((a)[0]), "r"((a)[1]), "r"((a)[2]), "r"((a)[3]),           \
                   "r"(b0), "r"(b1))

__global__ __launch_bounds__(256, 1) void conv2_mma_kernel(const float* __restrict__ bias) {
    extern __shared__ char cs[];
    uint32_t sb = smem_u32(cs);
    int tid = threadIdx.x;
    int wid = tid >> 5;
    int l = tid & 31;
    int o0 = blockIdx.y * 128;

    // ---- load geometry (cp.async) ----
    int seg = tid & 7;
    int r8 = tid >> 3;           // 0..31
    int abase[4];
#pragma unroll
    for (int q = 0; q < 4; q++) {
        int row = r8 + 32 * q;
        int pos = blockIdx.x * 128 + row;
        int b = pos / 36, s = pos % 36;
        int oy = s / 6, ox = s % 6;
        abase[q] = (b * 400 + oy * 40 + ox * 2) * 256 + seg * 8;
    }
    uint32_t ldst[4];
#pragma unroll
    for (int q = 0; q < 4; q++) ldst[q] = SWZ((r8 + 32 * q) * 128 + seg * 16);

    // ---- compute geometry (ldmatrix / mma) ----
    int mw = (wid & 1) * 64;     // warp m offset
    int nw = (wid >> 1) * 32;    // warp n offset
    int a_row = mw + (l & 7) + ((l >> 3) & 1) * 8;
    int a_kh = ((l >> 4) & 1) * 16;
    int xra = (a_row & 7) << 4;
    int b_row = nw + (l & 7) + ((l >> 4) & 1) * 8;
    int b_kh = ((l >> 3) & 1) * 16;
    int xrb = (b_row & 7) << 4;
    uint32_t arow128[4], brow128[2];
#pragma unroll
    for (int mt = 0; mt < 4; mt++) arow128[mt] = (a_row + mt * 16) * 128;
#pragma unroll
    for (int nt2 = 0; nt2 < 2; nt2++) brow128[nt2] = (b_row + nt2 * 16) * 128;

    float d[4][4][4];
#pragma unroll
    for (int mt = 0; mt < 4; mt++)
#pragma unroll
        for (int nt = 0; nt < 4; nt++)
#pragma unroll
            for (int r = 0; r < 4; r++) d[mt][nt][r] = 0.f;

#define LOAD_CHUNK(c, st)                                                       \
    do {                                                                        \
        int k_ = (c) >> 2, ic0_ = ((c) & 3) * 64;                               \
        int aoff_ = ((k_ / 9) * 20 + (k_ % 9)) * 256 + ic0_;                    \
        uint32_t sA_ = sb + SM_A(st), sB_ = sb + SM_B(st);                      \
        _Pragma("unroll")                                                       \
        for (int q = 0; q < 4; q++) {                                           \
            cp16(sA_ + ldst[q], g_h1hi + abase[q] + aoff_);                     \
            cp16(sA_ + 16384 + ldst[q], g_h1lo + abase[q] + aoff_);             \
        }                                                                       \
        int bs_ = (c) * 16384 + (o0 + r8) * 64 + seg * 8;                       \
        _Pragma("unroll")                                                       \
        for (int q = 0; q < 4; q++) {                                           \
            cp16(sB_ + ldst[q], g_w2hi + bs_ + q * 2048);                       \
            cp16(sB_ + 16384 + ldst[q], g_w2lo + bs_ + q * 2048);               \
        }                                                                       \
        asm volatile("cp.async.commit_group;" ::: "memory");                    \
    } while (0)

    LOAD_CHUNK(0, 0);
    LOAD_CHUNK(1, 1);

    for (int i = 0; i < NCHUNK; i++) {
        int cur = i % 3;
        if (i + 2 < NCHUNK) {
            LOAD_CHUNK(i + 2, (i + 2) % 3);
            asm volatile("cp.async.wait_group 2;" ::: "memory");
        } else if (i + 1 < NCHUNK) {
            asm volatile("cp.async.wait_group 1;" ::: "memory");
        } else {
            asm volatile("cp.async.wait_group 0;" ::: "memory");
        }
        __syncthreads();

        uint32_t sAh = sb + SM_A(cur), sAl = sAh + 16384;
        uint32_t sBh = sb + SM_B(cur), sBl = sBh + 16384;
#pragma unroll
        for (int ks = 0; ks < 4; ks++) {
            uint32_t aH[4][4], aL[4][4], bH[2][4], bL[2][4];
            uint32_t offA = (uint32_t)((ks * 32 + a_kh) ^ xra);
            uint32_t offB = (uint32_t)((ks * 32 + b_kh) ^ xrb);
#pragma unroll
            for (int mt = 0; mt < 4; mt++) {
                LDMX4(aH[mt], sAh + arow128[mt] + offA);
                LDMX4(aL[mt], sAl + arow128[mt] + offA);
            }
#pragma unroll
            for (int nt2 = 0; nt2 < 2; nt2++) {
                LDMX4(bH[nt2], sBh + brow128[nt2] + offB);
                LDMX4(bL[nt2], sBl + brow128[nt2] + offB);
            }
#pragma unroll
            for (int mt = 0; mt < 4; mt++) {
#pragma unroll
                for (int nt = 0; nt < 4; nt++) {
                    int n2 = nt >> 1, se = (nt & 1) * 2;
                    MMA(d[mt][nt], aH[mt], bH[n2][se], bH[n2][se + 1]);
                    MMA(d[mt][nt], aH[mt], bL[n2][se], bL[n2][se + 1]);
                    MMA(d[mt][nt], aL[mt], bH[n2][se], bH[n2][se + 1]);
                }
            }
        }
        __syncthreads();
    }

    // ---- epilogue: scatter to g_h2 [b][oc][36] with bias ----
    float bn[4][2];
#pragma unroll
    for (int nt = 0; nt < 4; nt++) {
        int n = o0 + nw + nt * 8 + (l & 3) * 2;
        bn[nt][0] = bias[n];
        bn[nt][1] = bias[n + 1];
    }
#pragma unroll
    for (int mt = 0; mt < 4; mt++) {
        int m0 = blockIdx.x * 128 + mw + mt * 16 + (l >> 2);
        int b0 = m0 / 36, s0 = m0 % 36;
        int m1 = m0 + 8;
        int b1 = m1 / 36, s1 = m1 % 36;
        int base0 = b0 * 9216 + s0;
        int base1 = b1 * 9216 + s1;
#pragma unroll
        for (int nt = 0; nt < 4; nt++) {
            int n = o0 + nw + nt * 8 + (l & 3) * 2;
            g_h2[base0 + n * 36]       = d[mt][nt][0] + bn[nt][0];
            g_h2[base0 + (n + 1) * 36] = d[mt][nt][1] + bn[nt][1];
            g_h2[base1 + n * 36]       = d[mt][nt][2] + bn[nt][0];
            g_h2[base1 + (n + 1) * 36] = d[mt][nt][3] + bn[nt][1];
        }
    }
}

// ============================================================
// capsule gather + squash: g_h2 -> g_u[B,1152,8]
// ============================================================
__global__ void usq_kernel() {
    int idx = blockIdx.x * 256 + threadIdx.x;
    if (idx >= BATCH * INCAPS) return;
    int b = idx / INCAPS, i = idx % INCAPS;
    int r = i / 36, s = i % 36;
    float v[8];
    float s2 = 0.f;
#pragma unroll
    for (int n = 0; n < 8; n++) {
        v[n] = g_h2[(b * 256 + n * 32 + r) * 36 + s];
        s2 += v[n] * v[n];
    }
    float scale = (s2 / (1.f + s2)) / sqrtf(s2 + EPSF);
#pragma unroll
    for (int n = 0; n < 8; n++) g_u[idx * 8 + n] = v[n] * scale;
}

// ============================================================
// u_hat[b,i,j,m] = sum_n W[i,j,n,m] * u[b,i,n]
// ============================================================
__global__ __launch_bounds__(160) void uhat_kernel(const float* __restrict__ W) {
    __shared__ __align__(16) float usm[BATCH * 8];
    int i = blockIdx.x;
    int t = threadIdx.x;
    int j = t >> 4, m = t & 15;
    float wreg[8];
#pragma unroll
    for (int n = 0; n < 8; n++) wreg[n] = W[i * 1280 + j * 128 + n * 16 + m];
    for (int idx = t; idx < BATCH * 8; idx += 160) {
        int bb = idx >> 3, n = idx & 7;
        usm[idx] = g_u[bb * (INCAPS * 8) + i * 8 + n];
    }
    __syncthreads();
    for (int bb = 0; bb < BATCH; bb++) {
        const float4* up = (const float4*)&usm[bb * 8];
        float4 u0 = up[0], u1 = up[1];
        float acc = wreg[0] * u0.x + wreg[1] * u0.y + wreg[2] * u0.z + wreg[3] * u0.w +
                    wreg[4] * u1.x + wreg[5] * u1.y + wreg[6] * u1.z + wreg[7] * u1.w;
        g_uhat[(long long)(bb * INCAPS + i) * 160 + t] = acc;
    }
}

// ============================================================
// dynamic routing (3 fused streaming passes)
// ============================================================
__device__ __forceinline__ float grp16_sum(float v) {
#pragma unroll
    for (int o = 8; o > 0; o >>= 1) v += __shfl_xor_sync(0xffffffffu, v, o, 16);
    return v;
}

__global__ __launch_bounds__(160) void routing_kernel(float* __restrict__ out) {
    int b = blockIdx.x;
    int t = threadIdx.x;
    int j = t >> 4;
    const float* __restrict__ uh = &g_uhat[(long long)b * INCAPS * 160];
    __shared__ float cn[OUTCAPS];
    __shared__ int predsm;

    float acc = 0.f;
#pragma unroll 8
    for (int i = 0; i < INCAPS; i++) acc += uh[i * 160 + t];
    float s = acc * (1.0f / 1152.0f);
    float n2 = grp16_sum(s * s);
    float v1 = s * (n2 / (1.f + n2)) / sqrtf(n2 + EPSF);

    float acc2 = 0.f, z2 = 0.f;
#pragma unroll 4
    for (int i = 0; i < INCAPS; i++) {
        float u = uh[i * 160 + t];
        float dd = grp16_sum(v1 * u);
        float e = __expf(dd);
        acc2 += e * u;
        z2 += e;
    }
    float s2v = acc2 / z2;
    float n2b = grp16_sum(s2v * s2v);
    float v2 = s2v * (n2b / (1.f + n2b)) / sqrtf(n2b + EPSF);

    float w12 = v1 + v2;
    float acc3 = 0.f, z3 = 0.f;
#pragma unroll 4
    for (int i = 0; i < INCAPS; i++) {
        float u = uh[i * 160 + t];
        float dd = grp16_sum(w12 * u);
        float e = __expf(dd);
        acc3 += e * u;
        z3 += e;
    }
    float s3 = acc3 / z3;
    float n2c = grp16_sum(s3 * s3);
    float v3 = s3 * (n2c / (1.f + n2c)) / sqrtf(n2c + EPSF);

    out[CAPS_OFF + b * 160 + t] = v3;

    float c2 = grp16_sum(v3 * v3);
    if ((t & 15) == 0) cn[j] = c2;
    __syncthreads();
    if (t == 0) {
        int best = 0;
        float bv = cn[0];
        for (int jj = 1; jj < OUTCAPS; jj++)
            if (cn[jj] > bv) { bv = cn[jj]; best = jj; }
        predsm = best;
        g_pred[b] = best;
        out[PRED_OFF + b] = (float)best;
    }
    __syncthreads();
    if (j == predsm) g_sel[b * 16 + (t & 15)] = v3;
}

// ============================================================
// decoder
// ============================================================
__global__ __launch_bounds__(256) void decoder_kernel(const float* __restrict__ d1w,
                                                      const float* __restrict__ d1b,
                                                      const float* __restrict__ d2w,
                                                      const float* __restrict__ d2b,
                                                      const float* __restrict__ d3w,
                                                      const float* __restrict__ d3b,
                                                      float* __restrict__ out) {
    __shared__ float r1s[4 * 512];
    __shared__ float r2s[4 * 1024];
    __shared__ float sel[4 * 16];
    __shared__ int pr[4];
    int b0 = blockIdx.x * 4;
    int t = threadIdx.x;
    if (t < 64) sel[t] = g_sel[(b0 + (t >> 4)) * 16 + (t & 15)];
    if (t < 4) pr[t] = g_pred[b0 + t];
    __syncthreads();

    for (int idx = t; idx < 4 * 512; idx += 256) {
        int g = idx >> 9, o = idx & 511;
        const float* wrow = &d1w[(pr[g] * 16) * 512 + o];
        float a = d1b[o];
#pragma unroll
        for (int k = 0; k < 16; k++) a += sel[g * 16 + k] * wrow[k * 512];
        r1s[idx] = fmaxf(a, 0.f);
    }
    __syncthreads();

#pragma unroll
    for (int c = 0; c < 2; c++) {
        int o1 = c * 512 + t, o2 = o1 + 256;
        float a[4][2];
#pragma unroll
        for (int g = 0; g < 4; g++) { a[g][0] = d2b[o1]; a[g][1] = d2b[o2]; }
        for (int k = 0; k < 512; k++) {
            float w1 = d2w[k * 1024 + o1];
            float w2 = d2w[k * 1024 + o2];
#pragma unroll
            for (int g = 0; g < 4; g++) {
                float r = r1s[g * 512 + k];
                a[g][0] += r * w1;
                a[g][1] += r * w2;
            }
        }
#pragma unroll
        for (int g = 0; g < 4; g++) {
            r2s[g * 1024 + o1] = fmaxf(a[g][0], 0.f);
            r2s[g * 1024 + o2] = fmaxf(a[g][1], 0.f);
        }
    }
    __syncthreads();

#pragma unroll
    for (int c = 0; c < 2; c++) {
        int o1 = c * 512 + t, o2 = o1 + 256;
        bool ok1 = o1 < 784, ok2 = o2 < 784;
        float a[4][2];
#pragma unroll
        for (int g = 0; g < 4; g++) {
            a[g][0] = ok1 ? d3b[o1] : 0.f;
            a[g][1] = ok2 ? d3b[o2] : 0.f;
        }
        for (int k = 0; k < 1024; k++) {
            float w1 = ok1 ? d3w[k * 784 + o1] : 0.f;
            float w2 = ok2 ? d3w[k * 784 + o2] : 0.f;
#pragma unroll
            for (int g = 0; g < 4; g++) {
                float r = r2s[g * 1024 + k];
                a[g][0] += r * w1;
                a[g][1] += r * w2;
            }
        }
#pragma unroll
        for (int g = 0; g < 4; g++) {
            if (ok1) out[RECON_OFF + (b0 + g) * 784 + o1] = 1.f / (1.f + expf(-a[g][0]));
            if (ok2) out[RECON_OFF + (b0 + g) * 784 + o2] = 1.f / (1.f + expf(-a[g][1]));
        }
    }
}

// ============================================================
extern "C" void kernel_launch(void* const* d_in, const int* in_sizes, int n_in,
                              void* d_out, int out_size) {
    const float* x   = (const float*)d_in[0];
    const float* c1w = (const float*)d_in[1];
    const float* c1b = (const float*)d_in[2];
    const float* c2w = (const float*)d_in[3];
    const float* c2b = (const float*)d_in[4];
    const float* W   = (const float*)d_in[5];
    const float* d1w = (const float*)d_in[6];
    const float* d1b = (const float*)d_in[7];
    const float* d2w = (const float*)d_in[8];
    const float* d2b = (const float*)d_in[9];
    const float* d3w = (const float*)d_in[10];
    const float* d3b = (const float*)d_in[11];
    float* out = (float*)d_out;

    cudaFuncSetAttribute(conv2_mma_kernel,
                         cudaFuncAttributeMaxDynamicSharedMemorySize, SMEM_BYTES);

    conv1_kernel<<<dim3(512, 16), 256>>>(x, c1w, c1b);
    repack_w2_kernel<<<(W2N + 255) / 256, 256>>>(c2w);
    conv2_mma_kernel<<<dim3(144, 2), 256, SMEM_BYTES>>>(c2b);
    usq_kernel<<<(BATCH * INCAPS + 255) / 256, 256>>>();
    uhat_kernel<<<INCAPS, 160>>>(W);
    routing_kernel<<<BATCH, 160>>>(out);
    decoder_kernel<<<BATCH / 4, 256>>>(d1w, d1b, d2w, d2b, d3w, d3b, out);
}

// round 7
// speedup vs baseline: 1.3930x; 1.3930x over previous
#include <cuda_runtime.h>
#include <cuda_bf16.h>
#include <math.h>
#include <stdint.h>

#define BATCH 512
#define INCAPS 1152
#define OUTCAPS 10
#define INDIM 8
#define OUTDIM 16
#define EPSF 1e-8f

// ---- scratch (device globals; no allocations allowed) ----
__device__ float g_h1[BATCH * 256 * 400];            // conv1 out [B,256,20,20]
__device__ float g_h2[BATCH * 256 * 36];             // conv2 out [B,256,6,6]
__device__ float g_u[BATCH * INCAPS * INDIM];        // squashed capsules [B,1152,8]
__device__ float g_uhat[(long long)BATCH * INCAPS * OUTCAPS * OUTDIM]; // [B,1152,10,16]
__device__ int   g_pred[BATCH];
__device__ float g_sel[BATCH * OUTDIM];

// tensor-core conv2 operands
#define H1N (BATCH * 400 * 256)
#define W2N (256 * 20736)
__device__ __align__(256) __nv_bfloat16 g_h1hi[H1N];   // NHWC hi [b][pix][c]
__device__ __align__(256) __nv_bfloat16 g_h1lo[H1N];   // NHWC lo
__device__ __align__(256) __nv_bfloat16 g_w2hi[W2N];   // [chunk c][oc][64 ic]
__device__ __align__(256) __nv_bfloat16 g_w2lo[W2N];

// output layout (float32): caps | recon | pred
#define CAPS_OFF  0
#define RECON_OFF (BATCH * OUTCAPS * OUTDIM)              // 81920
#define PRED_OFF  (RECON_OFF + BATCH * 784)               // 483328

// ============================================================
// conv1: x[B,1,28,28] (*) w[256,1,9,9] stride1 + bias, ReLU -> g_h1
// ============================================================
__global__ __launch_bounds__(256) void conv1_kernel(const float* __restrict__ x,
                                                    const float* __restrict__ w,
                                                    const float* __restrict__ bias) {
    __shared__ __align__(16) float img[784];
    __shared__ float wts[16 * 81];
    int b = blockIdx.x, c0 = blockIdx.y * 16, t = threadIdx.x;
    for (int i = t; i < 784; i += 256) img[i] = x[b * 784 + i];
    for (int i = t; i < 16 * 81; i += 256) wts[i] = w[c0 * 81 + i];
    __syncthreads();
    for (int idx = t; idx < 1600; idx += 256) {
        int cl = idx / 100;
        int rem = idx % 100;
        int oy = rem / 5;
        int ox0 = (rem % 5) * 4;
        float bb = bias[c0 + cl];
        float a0 = bb, a1 = bb, a2 = bb, a3 = bb;
        const float* wp = &wts[cl * 81];
#pragma unroll
        for (int ky = 0; ky < 9; ky++) {
            const float4* ip = (const float4*)&img[(oy + ky) * 28 + ox0];
            float4 q0 = ip[0], q1 = ip[1], q2 = ip[2];
            float v[12] = {q0.x, q0.y, q0.z, q0.w, q1.x, q1.y, q1.z, q1.w,
                           q2.x, q2.y, q2.z, q2.w};
#pragma unroll
            for (int kx = 0; kx < 9; kx++) {
                float wv = wp[ky * 9 + kx];
                a0 += wv * v[kx];
                a1 += wv * v[kx + 1];
                a2 += wv * v[kx + 2];
                a3 += wv * v[kx + 3];
            }
        }
        float* op = &g_h1[(b * 256 + c0 + cl) * 400 + oy * 20 + ox0];
        op[0] = fmaxf(a0, 0.f);
        op[1] = fmaxf(a1, 0.f);
        op[2] = fmaxf(a2, 0.f);
        op[3] = fmaxf(a3, 0.f);
    }
}

// ============================================================
// transpose + bf16 hi/lo split: g_h1 [b][c][400] -> NHWC [b][400][256]
// ============================================================
__global__ void h1_nhwc_kernel() {
    __shared__ float tile[32][33];
    int b = blockIdx.x, p0 = blockIdx.y * 32, c0 = blockIdx.z * 32;
    int tx = threadIdx.x, ty = threadIdx.y;
#pragma unroll
    for (int r = 0; r < 4; r++) {
        int c = c0 + ty + r * 8;
        int p = p0 + tx;
        tile[ty + r * 8][tx] = (p < 400) ? g_h1[(b * 256 + c) * 400 + p] : 0.f;
    }
    __syncthreads();
#pragma unroll
    for (int r = 0; r < 4; r++) {
        int p = p0 + ty + r * 8;
        if (p < 400) {
            float v = tile[tx][ty + r * 8];
            int c = c0 + tx;
            __nv_bfloat16 hi = __float2bfloat16(v);
            float lo = v - __bfloat162float(hi);
            g_h1hi[(b * 400 + p) * 256 + c] = hi;
            g_h1lo[(b * 400 + p) * 256 + c] = __float2bfloat16(lo);
        }
    }
}

// ============================================================
// weight repack: c2w[oc][ic][81] fp32 -> [c=k*4+icc][oc][ici] bf16 hi/lo
// ============================================================
__global__ void repack_w2_kernel(const float* __restrict__ w) {
    int idx = blockIdx.x * 256 + threadIdx.x;
    if (idx >= W2N) return;
    int ici = idx & 63;
    int oc = (idx >> 6) & 255;
    int c = idx >> 14;           // 0..323
    int k = c >> 2, icc = c & 3;
    int ic = icc * 64 + ici;
    float v = w[(oc * 256 + ic) * 81 + k];
    __nv_bfloat16 hi = __float2bfloat16(v);
    float lo = v - __bfloat162float(hi);
    g_w2hi[idx] = hi;
    g_w2lo[idx] = __float2bfloat16(lo);
}

// ============================================================
// conv2 via HMMA: D[pos 128][oc 128] tiles, K = 81*256 in chunks of 64.
// hi/lo bf16 split (3 MMAs per step). 3-stage cp.async pipeline with
// COMPILE-TIME stage indices (loop unrolled by 3) to keep addresses folded.
// ============================================================
#define NCHUNK 324
#define SMEM_STAGE 65536
#define SM_A(s) ((s) * SMEM_STAGE)          // Xhi 16K | Xlo 16K
#define SM_B(s) ((s) * SMEM_STAGE + 32768)  // Whi 16K | Wlo 16K
#define SMEM_BYTES (3 * SMEM_STAGE)
#define SWZ(x) ((x) ^ (((x) >> 3) & 0x70))

__device__ __forceinline__ uint32_t smem_u32(const void* p) {
    uint32_t a;
    asm("{ .reg .u64 t; cvta.to.shared.u64 t, %1; cvt.u32.u64 %0, t; }" : "=r"(a) : "l"(p));
    return a;
}
__device__ __forceinline__ void cp16(uint32_t dst, const void* src) {
    asm volatile("cp.async.cg.shared.global [%0], [%1], 16;" :: "r"(dst), "l"(src) : "memory");
}
#define LDMX4(r, addr)                                                          \
    asm volatile("ldmatrix.sync.aligned.m8n8.x4.shared.b16 {%0,%1,%2,%3}, [%4];" \
                 : "=r"((r)[0]), "=r"((r)[1]), "=r"((r)[2]), "=r"((r)[3])        \
                 : "r"(addr))
#define MMA(d, a, b0, b1)                                                        \
    asm volatile("mma.sync.aligned.m16n8k16.row.col.f32.bf16.bf16.f32 "          \
                 "{%0,%1,%2,%3}, {%4,%5,%6,%7}, {%8,%9}, {%0,%1,%2,%3};"         \
                 : "+f"((d)[0]), "+f"((d)[1]), "+f"((d)[2]), "+f"((d)[3])        \
                 : "r"((a)[0]), "r"((a)[1]), "r"((a)[2]), "r"((a)[3]),           \
                   "r"(b0), "r"(b1))

__global__ __launch_bounds__(256, 1) void conv2_mma_kernel(const float* __restrict__ bias) {
    extern __shared__ char cs[];
    uint32_t sb = smem_u32(cs);
    int tid = threadIdx.x;
    int wid = tid >> 5;
    int l = tid & 31;
    int o0 = blockIdx.y * 128;

    // ---- load geometry (cp.async) ----
    int seg = tid & 7;
    int r8 = tid >> 3;           // 0..31
    int abase[4];
#pragma unroll
    for (int q = 0; q < 4; q++) {
        int row = r8 + 32 * q;
        int pos = blockIdx.x * 128 + row;
        int b = pos / 36, s = pos % 36;
        int oy = s / 6, ox = s % 6;
        abase[q] = (b * 400 + oy * 40 + ox * 2) * 256 + seg * 8;
    }
    uint32_t ldst[4];
#pragma unroll
    for (int q = 0; q < 4; q++) ldst[q] = SWZ((r8 + 32 * q) * 128 + seg * 16);

    // ---- compute geometry (ldmatrix / mma) ----
    int mw = (wid & 1) * 64;     // warp m offset
    int nw = (wid >> 1) * 32;    // warp n offset
    int a_row = mw + (l & 7) + ((l >> 3) & 1) * 8;
    int a_kh = ((l >> 4) & 1) * 16;
    int xra = (a_row & 7) << 4;
    int b_row = nw + (l & 7) + ((l >> 4) & 1) * 8;
    int b_kh = ((l >> 3) & 1) * 16;
    int xrb = (b_row & 7) << 4;
    uint32_t arow128[4], brow128[2];
#pragma unroll
    for (int mt = 0; mt < 4; mt++) arow128[mt] = (a_row + mt * 16) * 128;
#pragma unroll
    for (int nt2 = 0; nt2 < 2; nt2++) brow128[nt2] = (b_row + nt2 * 16) * 128;

    float d[4][4][4];
#pragma unroll
    for (int mt = 0; mt < 4; mt++)
#pragma unroll
        for (int nt = 0; nt < 4; nt++)
#pragma unroll
            for (int r = 0; r < 4; r++) d[mt][nt][r] = 0.f;

#define LOAD_CHUNK(c, st)                                                       \
    do {                                                                        \
        int k_ = (c) >> 2, ic0_ = ((c) & 3) * 64;                               \
        int aoff_ = ((k_ / 9) * 20 + (k_ % 9)) * 256 + ic0_;                    \
        uint32_t sA_ = sb + SM_A(st), sB_ = sb + SM_B(st);                      \
        _Pragma("unroll")                                                       \
        for (int q = 0; q < 4; q++) {                                           \
            cp16(sA_ + ldst[q], g_h1hi + abase[q] + aoff_);                     \
            cp16(sA_ + 16384 + ldst[q], g_h1lo + abase[q] + aoff_);             \
        }                                                                       \
        int bs_ = (c) * 16384 + (o0 + r8) * 64 + seg * 8;                       \
        _Pragma("unroll")                                                       \
        for (int q = 0; q < 4; q++) {                                           \
            cp16(sB_ + ldst[q], g_w2hi + bs_ + q * 2048);                       \
            cp16(sB_ + 16384 + ldst[q], g_w2lo + bs_ + q * 2048);               \
        }                                                                       \
        asm volatile("cp.async.commit_group;" ::: "memory");                    \
    } while (0)

#define COMPUTE_STAGE(cur)                                                      \
    do {                                                                        \
        uint32_t sAh = sb + SM_A(cur), sAl = sAh + 16384;                       \
        uint32_t sBh = sb + SM_B(cur), sBl = sBh + 16384;                       \
        _Pragma("unroll")                                                       \
        for (int ks = 0; ks < 4; ks++) {                                        \
            uint32_t aH[4][4], aL[4][4], bH[2][4], bL[2][4];                    \
            uint32_t offA = (uint32_t)((ks * 32 + a_kh) ^ xra);                 \
            uint32_t offB = (uint32_t)((ks * 32 + b_kh) ^ xrb);                 \
            _Pragma("unroll")                                                   \
            for (int mt = 0; mt < 4; mt++) {                                    \
                LDMX4(aH[mt], sAh + arow128[mt] + offA);                        \
                LDMX4(aL[mt], sAl + arow128[mt] + offA);                        \
            }                                                                   \
            _Pragma("unroll")                                                   \
            for (int nt2 = 0; nt2 < 2; nt2++) {                                 \
                LDMX4(bH[nt2], sBh + brow128[nt2] + offB);                      \
                LDMX4(bL[nt2], sBl + brow128[nt2] + offB);                      \
            }                                                                   \
            _Pragma("unroll")                                                   \
            for (int mt = 0; mt < 4; mt++) {                                    \
                _Pragma("unroll")                                               \
                for (int nt = 0; nt < 4; nt++) {                                \
                    int n2 = nt >> 1, se = (nt & 1) * 2;                        \
                    MMA(d[mt][nt], aH[mt], bH[n2][se], bH[n2][se + 1]);         \
                    MMA(d[mt][nt], aH[mt], bL[n2][se], bL[n2][se + 1]);         \
                    MMA(d[mt][nt], aL[mt], bH[n2][se], bH[n2][se + 1]);         \
                }                                                               \
            }                                                                   \
        }                                                                       \
    } while (0)

// One pipeline iteration with literal stage indices. cur/pre = constants.
#define ITER(i, cur, pre)                                                       \
    do {                                                                        \
        if ((i) + 2 < NCHUNK) {                                                 \
            LOAD_CHUNK((i) + 2, pre);                                           \
            asm volatile("cp.async.wait_group 2;" ::: "memory");                \
        } else if ((i) + 1 < NCHUNK) {                                          \
            asm volatile("cp.async.wait_group 1;" ::: "memory");                \
        } else {                                                                \
            asm volatile("cp.async.wait_group 0;" ::: "memory");                \
        }                                                                       \
        __syncthreads();                                                        \
        COMPUTE_STAGE(cur);                                                     \
        __syncthreads();                                                        \
    } while (0)

    LOAD_CHUNK(0, 0);
    LOAD_CHUNK(1, 1);

    for (int i = 0; i < NCHUNK; i += 3) {
        ITER(i, 0, 2);
        ITER(i + 1, 1, 0);
        ITER(i + 2, 2, 1);
    }

    // ---- epilogue: scatter to g_h2 [b][oc][36] with bias ----
    float bn[4][2];
#pragma unroll
    for (int nt = 0; nt < 4; nt++) {
        int n = o0 + nw + nt * 8 + (l & 3) * 2;
        bn[nt][0] = bias[n];
        bn[nt][1] = bias[n + 1];
    }
#pragma unroll
    for (int mt = 0; mt < 4; mt++) {
        int m0 = blockIdx.x * 128 + mw + mt * 16 + (l >> 2);
        int b0 = m0 / 36, s0 = m0 % 36;
        int m1 = m0 + 8;
        int b1 = m1 / 36, s1 = m1 % 36;
        int base0 = b0 * 9216 + s0;
        int base1 = b1 * 9216 + s1;
#pragma unroll
        for (int nt = 0; nt < 4; nt++) {
            int n = o0 + nw + nt * 8 + (l & 3) * 2;
            g_h2[base0 + n * 36]       = d[mt][nt][0] + bn[nt][0];
            g_h2[base0 + (n + 1) * 36] = d[mt][nt][1] + bn[nt][1];
            g_h2[base1 + n * 36]       = d[mt][nt][2] + bn[nt][0];
            g_h2[base1 + (n + 1) * 36] = d[mt][nt][3] + bn[nt][1];
        }
    }
}

// ============================================================
// capsule gather + squash: g_h2 -> g_u[B,1152,8]
// ============================================================
__global__ void usq_kernel() {
    int idx = blockIdx.x * 256 + threadIdx.x;
    if (idx >= BATCH * INCAPS) return;
    int b = idx / INCAPS, i = idx % INCAPS;
    int r = i / 36, s = i % 36;
    float v[8];
    float s2 = 0.f;
#pragma unroll
    for (int n = 0; n < 8; n++) {
        v[n] = g_h2[(b * 256 + n * 32 + r) * 36 + s];
        s2 += v[n] * v[n];
    }
    float scale = (s2 / (1.f + s2)) / sqrtf(s2 + EPSF);
#pragma unroll
    for (int n = 0; n < 8; n++) g_u[idx * 8 + n] = v[n] * scale;
}

// ============================================================
// u_hat[b,i,j,m] = sum_n W[i,j,n,m] * u[b,i,n]
// ============================================================
__global__ __launch_bounds__(160) void uhat_kernel(const float* __restrict__ W) {
    __shared__ __align__(16) float usm[BATCH * 8];
    int i = blockIdx.x;
    int t = threadIdx.x;
    int j = t >> 4, m = t & 15;
    float wreg[8];
#pragma unroll
    for (int n = 0; n < 8; n++) wreg[n] = W[i * 1280 + j * 128 + n * 16 + m];
    for (int idx = t; idx < BATCH * 8; idx += 160) {
        int bb = idx >> 3, n = idx & 7;
        usm[idx] = g_u[bb * (INCAPS * 8) + i * 8 + n];
    }
    __syncthreads();
    for (int bb = 0; bb < BATCH; bb++) {
        const float4* up = (const float4*)&usm[bb * 8];
        float4 u0 = up[0], u1 = up[1];
        float acc = wreg[0] * u0.x + wreg[1] * u0.y + wreg[2] * u0.z + wreg[3] * u0.w +
                    wreg[4] * u1.x + wreg[5] * u1.y + wreg[6] * u1.z + wreg[7] * u1.w;
        g_uhat[(long long)(bb * INCAPS + i) * 160 + t] = acc;
    }
}

// ============================================================
// dynamic routing (3 fused streaming passes)
// ============================================================
__device__ __forceinline__ float grp16_sum(float v) {
#pragma unroll
    for (int o = 8; o > 0; o >>= 1) v += __shfl_xor_sync(0xffffffffu, v, o, 16);
    return v;
}

__global__ __launch_bounds__(160) void routing_kernel(float* __restrict__ out) {
    int b = blockIdx.x;
    int t = threadIdx.x;
    int j = t >> 4;
    const float* __restrict__ uh = &g_uhat[(long long)b * INCAPS * 160];
    __shared__ float cn[OUTCAPS];
    __shared__ int predsm;

    float acc = 0.f;
#pragma unroll 8
    for (int i = 0; i < INCAPS; i++) acc += uh[i * 160 + t];
    float s = acc * (1.0f / 1152.0f);
    float n2 = grp16_sum(s * s);
    float v1 = s * (n2 / (1.f + n2)) / sqrtf(n2 + EPSF);

    float acc2 = 0.f, z2 = 0.f;
#pragma unroll 4
    for (int i = 0; i < INCAPS; i++) {
        float u = uh[i * 160 + t];
        float dd = grp16_sum(v1 * u);
        float e = __expf(dd);
        acc2 += e * u;
        z2 += e;
    }
    float s2v = acc2 / z2;
    float n2b = grp16_sum(s2v * s2v);
    float v2 = s2v * (n2b / (1.f + n2b)) / sqrtf(n2b + EPSF);

    float w12 = v1 + v2;
    float acc3 = 0.f, z3 = 0.f;
#pragma unroll 4
    for (int i = 0; i < INCAPS; i++) {
        float u = uh[i * 160 + t];
        float dd = grp16_sum(w12 * u);
        float e = __expf(dd);
        acc3 += e * u;
        z3 += e;
    }
    float s3 = acc3 / z3;
    float n2c = grp16_sum(s3 * s3);
    float v3 = s3 * (n2c / (1.f + n2c)) / sqrtf(n2c + EPSF);

    out[CAPS_OFF + b * 160 + t] = v3;

    float c2 = grp16_sum(v3 * v3);
    if ((t & 15) == 0) cn[j] = c2;
    __syncthreads();
    if (t == 0) {
        int best = 0;
        float bv = cn[0];
        for (int jj = 1; jj < OUTCAPS; jj++)
            if (cn[jj] > bv) { bv = cn[jj]; best = jj; }
        predsm = best;
        g_pred[b] = best;
        out[PRED_OFF + b] = (float)best;
    }
    __syncthreads();
    if (j == predsm) g_sel[b * 16 + (t & 15)] = v3;
}

// ============================================================
// decoder
// ============================================================
__global__ __launch_bounds__(256) void decoder_kernel(const float* __restrict__ d1w,
                                                      const float* __restrict__ d1b,
                                                      const float* __restrict__ d2w,
                                                      const float* __restrict__ d2b,
                                                      const float* __restrict__ d3w,
                                                      const float* __restrict__ d3b,
                                                      float* __restrict__ out) {
    __shared__ float r1s[4 * 512];
    __shared__ float r2s[4 * 1024];
    __shared__ float sel[4 * 16];
    __shared__ int pr[4];
    int b0 = blockIdx.x * 4;
    int t = threadIdx.x;
    if (t < 64) sel[t] = g_sel[(b0 + (t >> 4)) * 16 + (t & 15)];
    if (t < 4) pr[t] = g_pred[b0 + t];
    __syncthreads();

    for (int idx = t; idx < 4 * 512; idx += 256) {
        int g = idx >> 9, o = idx & 511;
        const float* wrow = &d1w[(pr[g] * 16) * 512 + o];
        float a = d1b[o];
#pragma unroll
        for (int k = 0; k < 16; k++) a += sel[g * 16 + k] * wrow[k * 512];
        r1s[idx] = fmaxf(a, 0.f);
    }
    __syncthreads();

#pragma unroll
    for (int c = 0; c < 2; c++) {
        int o1 = c * 512 + t, o2 = o1 + 256;
        float a[4][2];
#pragma unroll
        for (int g = 0; g < 4; g++) { a[g][0] = d2b[o1]; a[g][1] = d2b[o2]; }
        for (int k = 0; k < 512; k++) {
            float w1 = d2w[k * 1024 + o1];
            float w2 = d2w[k * 1024 + o2];
#pragma unroll
            for (int g = 0; g < 4; g++) {
                float r = r1s[g * 512 + k];
                a[g][0] += r * w1;
                a[g][1] += r * w2;
            }
        }
#pragma unroll
        for (int g = 0; g < 4; g++) {
            r2s[g * 1024 + o1] = fmaxf(a[g][0], 0.f);
            r2s[g * 1024 + o2] = fmaxf(a[g][1], 0.f);
        }
    }
    __syncthreads();

#pragma unroll
    for (int c = 0; c < 2; c++) {
        int o1 = c * 512 + t, o2 = o1 + 256;
        bool ok1 = o1 < 784, ok2 = o2 < 784;
        float a[4][2];
#pragma unroll
        for (int g = 0; g < 4; g++) {
            a[g][0] = ok1 ? d3b[o1] : 0.f;
            a[g][1] = ok2 ? d3b[o2] : 0.f;
        }
        for (int k = 0; k < 1024; k++) {
            float w1 = ok1 ? d3w[k * 784 + o1] : 0.f;
            float w2 = ok2 ? d3w[k * 784 + o2] : 0.f;
#pragma unroll
            for (int g = 0; g < 4; g++) {
                float r = r2s[g * 1024 + k];
                a[g][0] += r * w1;
                a[g][1] += r * w2;
            }
        }
#pragma unroll
        for (int g = 0; g < 4; g++) {
            if (ok1) out[RECON_OFF + (b0 + g) * 784 + o1] = 1.f / (1.f + expf(-a[g][0]));
            if (ok2) out[RECON_OFF + (b0 + g) * 784 + o2] = 1.f / (1.f + expf(-a[g][1]));
        }
    }
}

// ============================================================
extern "C" void kernel_launch(void* const* d_in, const int* in_sizes, int n_in,
                              void* d_out, int out_size) {
    const float* x   = (const float*)d_in[0];
    const float* c1w = (const float*)d_in[1];
    const float* c1b = (const float*)d_in[2];
    const float* c2w = (const float*)d_in[3];
    const float* c2b = (const float*)d_in[4];
    const float* W   = (const float*)d_in[5];
    const float* d1w = (const float*)d_in[6];
    const float* d1b = (const float*)d_in[7];
    const float* d2w = (const float*)d_in[8];
    const float* d2b = (const float*)d_in[9];
    const float* d3w = (const float*)d_in[10];
    const float* d3b = (const float*)d_in[11];
    float* out = (float*)d_out;

    cudaFuncSetAttribute(conv2_mma_kernel,
                         cudaFuncAttributeMaxDynamicSharedMemorySize, SMEM_BYTES);

    conv1_kernel<<<dim3(512, 16), 256>>>(x, c1w, c1b);
    h1_nhwc_kernel<<<dim3(512, 13, 8), dim3(32, 8)>>>();
    repack_w2_kernel<<<(W2N + 255) / 256, 256>>>(c2w);
    conv2_mma_kernel<<<dim3(144, 2), 256, SMEM_BYTES>>>(c2b);
    usq_kernel<<<(BATCH * INCAPS + 255) / 256, 256>>>();
    uhat_kernel<<<INCAPS, 160>>>(W);
    routing_kernel<<<BATCH, 160>>>(out);
    decoder_kernel<<<BATCH / 4, 256>>>(d1w, d1b, d2w, d2b, d3w, d3b, out);
}

// round 8
// speedup vs baseline: 1.4215x; 1.0205x over previous
#include <cuda_runtime.h>
#include <cuda_bf16.h>
#include <math.h>
#include <stdint.h>

#define BATCH 512
#define INCAPS 1152
#define OUTCAPS 10
#define INDIM 8
#define OUTDIM 16
#define EPSF 1e-8f

// ---- scratch (device globals; no allocations allowed) ----
__device__ float g_h2[BATCH * 256 * 36];             // conv2 out [B,256,6,6]
__device__ float g_u[BATCH * INCAPS * INDIM];        // squashed capsules [B,1152,8]
__device__ float g_uhat[(long long)BATCH * INCAPS * OUTCAPS * OUTDIM]; // [B,1152,10,16]
__device__ int   g_pred[BATCH];
__device__ float g_sel[BATCH * OUTDIM];

// tensor-core conv2 operands
#define H1N (BATCH * 400 * 256)
#define W2N (256 * 20736)
__device__ __align__(256) __nv_bfloat16 g_h1hi[H1N];   // NHWC hi [b][pix][c]
__device__ __align__(256) __nv_bfloat16 g_h1lo[H1N];   // NHWC lo
__device__ __align__(256) __nv_bfloat16 g_w2hi[W2N];   // [chunk c][oc][64 ic]
__device__ __align__(256) __nv_bfloat16 g_w2lo[W2N];

// output layout (float32): caps | recon | pred
#define CAPS_OFF  0
#define RECON_OFF (BATCH * OUTCAPS * OUTDIM)              // 81920
#define PRED_OFF  (RECON_OFF + BATCH * 784)               // 483328

// ============================================================
// conv1 fused: x (*) w stride1 + bias, ReLU -> NHWC bf16 hi/lo directly.
// Per block: (image b, 16 channels). Results staged in padded smem, then
// written as [pix][16ch] 32B rows (2x uint4 per array).
// ============================================================
__global__ __launch_bounds__(256) void conv1_kernel(const float* __restrict__ x,
                                                    const float* __restrict__ w,
                                                    const float* __restrict__ bias) {
    __shared__ __align__(16) float img[784];
    __shared__ float wts[16 * 81];
    __shared__ float stage[16 * 401];
    int b = blockIdx.x, c0 = blockIdx.y * 16, t = threadIdx.x;
    for (int i = t; i < 784; i += 256) img[i] = x[b * 784 + i];
    for (int i = t; i < 16 * 81; i += 256) wts[i] = w[c0 * 81 + i];
    __syncthreads();
    for (int idx = t; idx < 1600; idx += 256) {
        int cl = idx / 100;
        int rem = idx % 100;
        int oy = rem / 5;
        int ox0 = (rem % 5) * 4;
        float bb = bias[c0 + cl];
        float a0 = bb, a1 = bb, a2 = bb, a3 = bb;
        const float* wp = &wts[cl * 81];
#pragma unroll
        for (int ky = 0; ky < 9; ky++) {
            const float4* ip = (const float4*)&img[(oy + ky) * 28 + ox0];
            float4 q0 = ip[0], q1 = ip[1], q2 = ip[2];
            float v[12] = {q0.x, q0.y, q0.z, q0.w, q1.x, q1.y, q1.z, q1.w,
                           q2.x, q2.y, q2.z, q2.w};
#pragma unroll
            for (int kx = 0; kx < 9; kx++) {
                float wv = wp[ky * 9 + kx];
                a0 += wv * v[kx];
                a1 += wv * v[kx + 1];
                a2 += wv * v[kx + 2];
                a3 += wv * v[kx + 3];
            }
        }
        float* sp = &stage[cl * 401 + oy * 20 + ox0];
        sp[0] = fmaxf(a0, 0.f);
        sp[1] = fmaxf(a1, 0.f);
        sp[2] = fmaxf(a2, 0.f);
        sp[3] = fmaxf(a3, 0.f);
    }
    __syncthreads();
    for (int p = t; p < 400; p += 256) {
        uint32_t hp[8], lp[8];
#pragma unroll
        for (int k = 0; k < 8; k++) {
            float v0 = stage[(2 * k) * 401 + p];
            float v1 = stage[(2 * k + 1) * 401 + p];
            __nv_bfloat16 h0 = __float2bfloat16(v0);
            __nv_bfloat16 h1 = __float2bfloat16(v1);
            float l0 = v0 - __bfloat162float(h0);
            float l1 = v1 - __bfloat162float(h1);
            __nv_bfloat16 lo0 = __float2bfloat16(l0);
            __nv_bfloat16 lo1 = __float2bfloat16(l1);
            hp[k] = (uint32_t)__bfloat16_as_ushort(h0) |
                    ((uint32_t)__bfloat16_as_ushort(h1) << 16);
            lp[k] = (uint32_t)__bfloat16_as_ushort(lo0) |
                    ((uint32_t)__bfloat16_as_ushort(lo1) << 16);
        }
        int off = (b * 400 + p) * 256 + c0;
        uint4* dh = (uint4*)(g_h1hi + off);
        uint4* dl = (uint4*)(g_h1lo + off);
        dh[0] = make_uint4(hp[0], hp[1], hp[2], hp[3]);
        dh[1] = make_uint4(hp[4], hp[5], hp[6], hp[7]);
        dl[0] = make_uint4(lp[0], lp[1], lp[2], lp[3]);
        dl[1] = make_uint4(lp[4], lp[5], lp[6], lp[7]);
    }
}

// ============================================================
// weight repack: c2w[oc][ic][81] fp32 -> [c=k*4+icc][oc][ici] bf16 hi/lo
// ============================================================
__global__ void repack_w2_kernel(const float* __restrict__ w) {
    int idx = blockIdx.x * 256 + threadIdx.x;
    if (idx >= W2N) return;
    int ici = idx & 63;
    int oc = (idx >> 6) & 255;
    int c = idx >> 14;           // 0..323
    int k = c >> 2, icc = c & 3;
    int ic = icc * 64 + ici;
    float v = w[(oc * 256 + ic) * 81 + k];
    __nv_bfloat16 hi = __float2bfloat16(v);
    float lo = v - __bfloat162float(hi);
    g_w2hi[idx] = hi;
    g_w2lo[idx] = __float2bfloat16(lo);
}

// ============================================================
// conv2 via HMMA (mma.sync m16n8k16 bf16): D[pos 128][oc 128] tiles.
// K = 81*256 in chunks of 64. hi/lo bf16 split (3 MMAs per step).
// CTA 256 threads = 8 warps of 64x32 warp tiles. cp.async double buffer.
// (exact R4 code — known 3042us)
// ============================================================
#define NCHUNK 324
#define SMEM_STAGE 65536
#define SM_A(s) ((s) * SMEM_STAGE)          // Xhi 16K | Xlo 16K
#define SM_B(s) ((s) * SMEM_STAGE + 32768)  // Whi 16K | Wlo 16K
#define SMEM_BYTES (2 * SMEM_STAGE)
#define SWZ(x) ((x) ^ (((x) >> 3) & 0x70))

__device__ __forceinline__ uint32_t smem_u32(const void* p) {
    uint32_t a;
    asm("{ .reg .u64 t; cvta.to.shared.u64 t, %1; cvt.u32.u64 %0, t; }" : "=r"(a) : "l"(p));
    return a;
}
__device__ __forceinline__ void cp16(uint32_t dst, const void* src) {
    asm volatile("cp.async.cg.shared.global [%0], [%1], 16;" :: "r"(dst), "l"(src) : "memory");
}
#define LDMX4(r, addr)                                                          \
    asm volatile("ldmatrix.sync.aligned.m8n8.x4.shared.b16 {%0,%1,%2,%3}, [%4];" \
                 : "=r"((r)[0]), "=r"((r)[1]), "=r"((r)[2]), "=r"((r)[3])        \
                 : "r"(addr))
#define MMA(d, a, b0, b1)                                                        \
    asm volatile("mma.sync.aligned.m16n8k16.row.col.f32.bf16.bf16.f32 "          \
                 "{%0,%1,%2,%3}, {%4,%5,%6,%7}, {%8,%9}, {%0,%1,%2,%3};"         \
                 : "+f"((d)[0]), "+f"((d)[1]), "+f"((d)[2]), "+f"((d)[3])        \
                 : "r"((a)[0]), "r"((a)[1]), "r"((a)[2]), "r"((a)[3]),           \
                   "r"(b0), "r"(b1))

__global__ __launch_bounds__(256, 1) void conv2_mma_kernel(const float* __restrict__ bias) {
    extern __shared__ char cs[];
    uint32_t sb = smem_u32(cs);
    int tid = threadIdx.x;
    int wid = tid >> 5;
    int l = tid & 31;
    int o0 = blockIdx.y * 128;

    // ---- load geometry (cp.async) ----
    int seg = tid & 7;
    int r8 = tid >> 3;           // 0..31
    int abase[4];
#pragma unroll
    for (int q = 0; q < 4; q++) {
        int row = r8 + 32 * q;
        int pos = blockIdx.x * 128 + row;
        int b = pos / 36, s = pos % 36;
        int oy = s / 6, ox = s % 6;
        abase[q] = (b * 400 + oy * 40 + ox * 2) * 256 + seg * 8;
    }
    uint32_t ldst[4];
#pragma unroll
    for (int q = 0; q < 4; q++) ldst[q] = SWZ((r8 + 32 * q) * 128 + seg * 16);

    // ---- compute geometry (ldmatrix / mma) ----
    int mw = (wid & 1) * 64;     // warp m offset
    int nw = (wid >> 1) * 32;    // warp n offset
    int a_row = mw + (l & 7) + ((l >> 3) & 1) * 8;
    int a_kh = ((l >> 4) & 1) * 16;
    int xra = (a_row & 7) << 4;
    int b_row = nw + (l & 7) + ((l >> 4) & 1) * 8;
    int b_kh = ((l >> 3) & 1) * 16;
    int xrb = (b_row & 7) << 4;
    uint32_t arow128[4], brow128[2];
#pragma unroll
    for (int mt = 0; mt < 4; mt++) arow128[mt] = (a_row + mt * 16) * 128;
#pragma unroll
    for (int nt2 = 0; nt2 < 2; nt2++) brow128[nt2] = (b_row + nt2 * 16) * 128;

    float d[4][4][4];
#pragma unroll
    for (int mt = 0; mt < 4; mt++)
#pragma unroll
        for (int nt = 0; nt < 4; nt++)
#pragma unroll
            for (int r = 0; r < 4; r++) d[mt][nt][r] = 0.f;

    // ---- preload chunk 0 ----
    {
        uint32_t sA = sb + SM_A(0), sB = sb + SM_B(0);
#pragma unroll
        for (int q = 0; q < 4; q++) {
            cp16(sA + ldst[q], g_h1hi + abase[q]);
            cp16(sA + 16384 + ldst[q], g_h1lo + abase[q]);
        }
        int bs = (o0 + r8) * 64 + seg * 8;
#pragma unroll
        for (int q = 0; q < 4; q++) {
            cp16(sB + ldst[q], g_w2hi + bs + q * 2048);
            cp16(sB + 16384 + ldst[q], g_w2lo + bs + q * 2048);
        }
        asm volatile("cp.async.commit_group;" ::: "memory");
    }

    for (int i = 0; i < NCHUNK; i++) {
        int cur = i & 1;
        if (i + 1 < NCHUNK) {
            int c = i + 1;
            int k = c >> 2, ic0 = (c & 3) * 64;
            int aoff = ((k / 9) * 20 + (k % 9)) * 256 + ic0;
            uint32_t sA = sb + SM_A(cur ^ 1), sB = sb + SM_B(cur ^ 1);
#pragma unroll
            for (int q = 0; q < 4; q++) {
                cp16(sA + ldst[q], g_h1hi + abase[q] + aoff);
                cp16(sA + 16384 + ldst[q], g_h1lo + abase[q] + aoff);
            }
            int bs = c * 16384 + (o0 + r8) * 64 + seg * 8;
#pragma unroll
            for (int q = 0; q < 4; q++) {
                cp16(sB + ldst[q], g_w2hi + bs + q * 2048);
                cp16(sB + 16384 + ldst[q], g_w2lo + bs + q * 2048);
            }
            asm volatile("cp.async.commit_group;" ::: "memory");
            asm volatile("cp.async.wait_group 1;" ::: "memory");
        } else {
            asm volatile("cp.async.wait_group 0;" ::: "memory");
        }
        __syncthreads();

        uint32_t sAh = sb + SM_A(cur), sAl = sAh + 16384;
        uint32_t sBh = sb + SM_B(cur), sBl = sBh + 16384;
#pragma unroll
        for (int ks = 0; ks < 4; ks++) {
            uint32_t aH[4][4], aL[4][4], bH[2][4], bL[2][4];
            uint32_t offA = (uint32_t)((ks * 32 + a_kh) ^ xra);
            uint32_t offB = (uint32_t)((ks * 32 + b_kh) ^ xrb);
#pragma unroll
            for (int mt = 0; mt < 4; mt++) {
                LDMX4(aH[mt], sAh + arow128[mt] + offA);
                LDMX4(aL[mt], sAl + arow128[mt] + offA);
            }
#pragma unroll
            for (int nt2 = 0; nt2 < 2; nt2++) {
                LDMX4(bH[nt2], sBh + brow128[nt2] + offB);
                LDMX4(bL[nt2], sBl + brow128[nt2] + offB);
            }
#pragma unroll
            for (int mt = 0; mt < 4; mt++) {
#pragma unroll
                for (int nt = 0; nt < 4; nt++) {
                    int n2 = nt >> 1, se = (nt & 1) * 2;
                    MMA(d[mt][nt], aH[mt], bH[n2][se], bH[n2][se + 1]);
                    MMA(d[mt][nt], aH[mt], bL[n2][se], bL[n2][se + 1]);
                    MMA(d[mt][nt], aL[mt], bH[n2][se], bH[n2][se + 1]);
                }
            }
        }
        __syncthreads();
    }

    // ---- epilogue: scatter to g_h2 [b][oc][36] with bias ----
    float bn[4][2];
#pragma unroll
    for (int nt = 0; nt < 4; nt++) {
        int n = o0 + nw + nt * 8 + (l & 3) * 2;
        bn[nt][0] = bias[n];
        bn[nt][1] = bias[n + 1];
    }
#pragma unroll
    for (int mt = 0; mt < 4; mt++) {
        int m0 = blockIdx.x * 128 + mw + mt * 16 + (l >> 2);
        int b0 = m0 / 36, s0 = m0 % 36;
        int m1 = m0 + 8;
        int b1 = m1 / 36, s1 = m1 % 36;
        int base0 = b0 * 9216 + s0;
        int base1 = b1 * 9216 + s1;
#pragma unroll
        for (int nt = 0; nt < 4; nt++) {
            int n = o0 + nw + nt * 8 + (l & 3) * 2;
            g_h2[base0 + n * 36]       = d[mt][nt][0] + bn[nt][0];
            g_h2[base0 + (n + 1) * 36] = d[mt][nt][1] + bn[nt][1];
            g_h2[base1 + n * 36]       = d[mt][nt][2] + bn[nt][0];
            g_h2[base1 + (n + 1) * 36] = d[mt][nt][3] + bn[nt][1];
        }
    }
}

// ============================================================
// capsule gather + squash: g_h2 -> g_u[B,1152,8]
// ============================================================
__global__ void usq_kernel() {
    int idx = blockIdx.x * 256 + threadIdx.x;
    if (idx >= BATCH * INCAPS) return;
    int b = idx / INCAPS, i = idx % INCAPS;
    int r = i / 36, s = i % 36;
    float v[8];
    float s2 = 0.f;
#pragma unroll
    for (int n = 0; n < 8; n++) {
        v[n] = g_h2[(b * 256 + n * 32 + r) * 36 + s];
        s2 += v[n] * v[n];
    }
    float scale = (s2 / (1.f + s2)) / sqrtf(s2 + EPSF);
#pragma unroll
    for (int n = 0; n < 8; n++) g_u[idx * 8 + n] = v[n] * scale;
}

// ============================================================
// u_hat[b,i,j,m] = sum_n W[i,j,n,m] * u[b,i,n]
// ============================================================
__global__ __launch_bounds__(160) void uhat_kernel(const float* __restrict__ W) {
    __shared__ __align__(16) float usm[BATCH * 8];
    int i = blockIdx.x;
    int t = threadIdx.x;
    int j = t >> 4, m = t & 15;
    float wreg[8];
#pragma unroll
    for (int n = 0; n < 8; n++) wreg[n] = W[i * 1280 + j * 128 + n * 16 + m];
    for (int idx = t; idx < BATCH * 8; idx += 160) {
        int bb = idx >> 3, n = idx & 7;
        usm[idx] = g_u[bb * (INCAPS * 8) + i * 8 + n];
    }
    __syncthreads();
    for (int bb = 0; bb < BATCH; bb++) {
        const float4* up = (const float4*)&usm[bb * 8];
        float4 u0 = up[0], u1 = up[1];
        float acc = wreg[0] * u0.x + wreg[1] * u0.y + wreg[2] * u0.z + wreg[3] * u0.w +
                    wreg[4] * u1.x + wreg[5] * u1.y + wreg[6] * u1.z + wreg[7] * u1.w;
        g_uhat[(long long)(bb * INCAPS + i) * 160 + t] = acc;
    }
}

// ============================================================
// dynamic routing (3 fused streaming passes)
// ============================================================
__device__ __forceinline__ float grp16_sum(float v) {
#pragma unroll
    for (int o = 8; o > 0; o >>= 1) v += __shfl_xor_sync(0xffffffffu, v, o, 16);
    return v;
}

__global__ __launch_bounds__(160) void routing_kernel(float* __restrict__ out) {
    int b = blockIdx.x;
    int t = threadIdx.x;
    int j = t >> 4;
    const float* __restrict__ uh = &g_uhat[(long long)b * INCAPS * 160];
    __shared__ float cn[OUTCAPS];
    __shared__ int predsm;

    float acc = 0.f;
#pragma unroll 8
    for (int i = 0; i < INCAPS; i++) acc += uh[i * 160 + t];
    float s = acc * (1.0f / 1152.0f);
    float n2 = grp16_sum(s * s);
    float v1 = s * (n2 / (1.f + n2)) / sqrtf(n2 + EPSF);

    float acc2 = 0.f, z2 = 0.f;
#pragma unroll 4
    for (int i = 0; i < INCAPS; i++) {
        float u = uh[i * 160 + t];
        float dd = grp16_sum(v1 * u);
        float e = __expf(dd);
        acc2 += e * u;
        z2 += e;
    }
    float s2v = acc2 / z2;
    float n2b = grp16_sum(s2v * s2v);
    float v2 = s2v * (n2b / (1.f + n2b)) / sqrtf(n2b + EPSF);

    float w12 = v1 + v2;
    float acc3 = 0.f, z3 = 0.f;
#pragma unroll 4
    for (int i = 0; i < INCAPS; i++) {
        float u = uh[i * 160 + t];
        float dd = grp16_sum(w12 * u);
        float e = __expf(dd);
        acc3 += e * u;
        z3 += e;
    }
    float s3 = acc3 / z3;
    float n2c = grp16_sum(s3 * s3);
    float v3 = s3 * (n2c / (1.f + n2c)) / sqrtf(n2c + EPSF);

    out[CAPS_OFF + b * 160 + t] = v3;

    float c2 = grp16_sum(v3 * v3);
    if ((t & 15) == 0) cn[j] = c2;
    __syncthreads();
    if (t == 0) {
        int best = 0;
        float bv = cn[0];
        for (int jj = 1; jj < OUTCAPS; jj++)
            if (cn[jj] > bv) { bv = cn[jj]; best = jj; }
        predsm = best;
        g_pred[b] = best;
        out[PRED_OFF + b] = (float)best;
    }
    __syncthreads();
    if (j == predsm) g_sel[b * 16 + (t & 15)] = v3;
}

// ============================================================
// decoder
// ============================================================
__global__ __launch_bounds__(256) void decoder_kernel(const float* __restrict__ d1w,
                                                      const float* __restrict__ d1b,
                                                      const float* __restrict__ d2w,
                                                      const float* __restrict__ d2b,
                                                      const float* __restrict__ d3w,
                                                      const float* __restrict__ d3b,
                                                      float* __restrict__ out) {
    __shared__ float r1s[4 * 512];
    __shared__ float r2s[4 * 1024];
    __shared__ float sel[4 * 16];
    __shared__ int pr[4];
    int b0 = blockIdx.x * 4;
    int t = threadIdx.x;
    if (t < 64) sel[t] = g_sel[(b0 + (t >> 4)) * 16 + (t & 15)];
    if (t < 4) pr[t] = g_pred[b0 + t];
    __syncthreads();

    for (int idx = t; idx < 4 * 512; idx += 256) {
        int g = idx >> 9, o = idx & 511;
        const float* wrow = &d1w[(pr[g] * 16) * 512 + o];
        float a = d1b[o];
#pragma unroll
        for (int k = 0; k < 16; k++) a += sel[g * 16 + k] * wrow[k * 512];
        r1s[idx] = fmaxf(a, 0.f);
    }
    __syncthreads();

#pragma unroll
    for (int c = 0; c < 2; c++) {
        int o1 = c * 512 + t, o2 = o1 + 256;
        float a[4][2];
#pragma unroll
        for (int g = 0; g < 4; g++) { a[g][0] = d2b[o1]; a[g][1] = d2b[o2]; }
        for (int k = 0; k < 512; k++) {
            float w1 = d2w[k * 1024 + o1];
            float w2 = d2w[k * 1024 + o2];
#pragma unroll
            for (int g = 0; g < 4; g++) {
                float r = r1s[g * 512 + k];
                a[g][0] += r * w1;
                a[g][1] += r * w2;
            }
        }
#pragma unroll
        for (int g = 0; g < 4; g++) {
            r2s[g * 1024 + o1] = fmaxf(a[g][0], 0.f);
            r2s[g * 1024 + o2] = fmaxf(a[g][1], 0.f);
        }
    }
    __syncthreads();

#pragma unroll
    for (int c = 0; c < 2; c++) {
        int o1 = c * 512 + t, o2 = o1 + 256;
        bool ok1 = o1 < 784, ok2 = o2 < 784;
        float a[4][2];
#pragma unroll
        for (int g = 0; g < 4; g++) {
            a[g][0] = ok1 ? d3b[o1] : 0.f;
            a[g][1] = ok2 ? d3b[o2] : 0.f;
        }
        for (int k = 0; k < 1024; k++) {
            float w1 = ok1 ? d3w[k * 784 + o1] : 0.f;
            float w2 = ok2 ? d3w[k * 784 + o2] : 0.f;
#pragma unroll
            for (int g = 0; g < 4; g++) {
                float r = r2s[g * 1024 + k];
                a[g][0] += r * w1;
                a[g][1] += r * w2;
            }
        }
#pragma unroll
        for (int g = 0; g < 4; g++) {
            if (ok1) out[RECON_OFF + (b0 + g) * 784 + o1] = 1.f / (1.f + expf(-a[g][0]));
            if (ok2) out[RECON_OFF + (b0 + g) * 784 + o2] = 1.f / (1.f + expf(-a[g][1]));
        }
    }
}

// ============================================================
extern "C" void kernel_launch(void* const* d_in, const int* in_sizes, int n_in,
                              void* d_out, int out_size) {
    const float* x   = (const float*)d_in[0];
    const float* c1w = (const float*)d_in[1];
    const float* c1b = (const float*)d_in[2];
    const float* c2w = (const float*)d_in[3];
    const float* c2b = (const float*)d_in[4];
    const float* W   = (const float*)d_in[5];
    const float* d1w = (const float*)d_in[6];
    const float* d1b = (const float*)d_in[7];
    const float* d2w = (const float*)d_in[8];
    const float* d2b = (const float*)d_in[9];
    const float* d3w = (const float*)d_in[10];
    const float* d3b = (const float*)d_in[11];
    float* out = (float*)d_out;

    cudaFuncSetAttribute(conv2_mma_kernel,
                         cudaFuncAttributeMaxDynamicSharedMemorySize, SMEM_BYTES);

    conv1_kernel<<<dim3(512, 16), 256>>>(x, c1w, c1b);
    repack_w2_kernel<<<(W2N + 255) / 256, 256>>>(c2w);
    conv2_mma_kernel<<<dim3(144, 2), 256, SMEM_BYTES>>>(c2b);
    usq_kernel<<<(BATCH * INCAPS + 255) / 256, 256>>>();
    uhat_kernel<<<INCAPS, 160>>>(W);
    routing_kernel<<<BATCH, 160>>>(out);
    decoder_kernel<<<BATCH / 4, 256>>>(d1w, d1b, d2w, d2b, d3w, d3b, out);
}